// round 1
// baseline (speedup 1.0000x reference)
#include <cuda_runtime.h>
#include <cuda_bf16.h>
#include <math.h>
#include <stdint.h>

// Problem constants
constexpr int B_   = 4096;          // batch
constexpr int G_   = 1024;          // gate width g
constexpr int KDIM = 2048;          // IN + g
constexpr int NDIM = 5120;          // out_dim = 5*g
constexpr long long OUT_REC = 0;                         // recurrent_hidden base
constexpr long long OUT_OH  = (long long)B_ * 4 * G_;    // output_hidden base (16777216)

// Static scratch (no allocations allowed)
__device__ float  g_A[(size_t)B_ * KDIM];     // [input | h_fl]  (33.5 MB)
__device__ float  g_zg[(size_t)B_ * NDIM];    // pre-activations (83.9 MB)
__device__ double g_part[2 * 16384];          // per-block log partial sums

__device__ __forceinline__ float sigm(float x) {
    return 1.0f / (1.0f + expf(-x));
}

// ---------------------------------------------------------------------------
// Pack A = [input | h2 * 2^-23]
// ---------------------------------------------------------------------------
__global__ void prep_kernel(const float* __restrict__ inp,
                            const int*   __restrict__ hidden)
{
    int idx = blockIdx.x * 256 + threadIdx.x;      // 0 .. B_*G_-1
    int i = idx >> 10;
    int j = idx & 1023;
    g_A[(size_t)i * KDIM + j]       = inp[idx];
    g_A[(size_t)i * KDIM + G_ + j]  = (float)hidden[(size_t)i * 4 * G_ + G_ + j] * (1.0f / 8388608.0f);
}

// ---------------------------------------------------------------------------
// fp32 SGEMM:  g_zg = g_A (B_ x KDIM) @ W^T (NDIM x KDIM) + bias
// 128x128x16 tile, 8x8 microtile, 256 threads, register-staged prefetch
// ---------------------------------------------------------------------------
__global__ __launch_bounds__(256, 2)
void sgemm_kernel(const float* __restrict__ Wmat,
                  const float* __restrict__ bias)
{
    __shared__ float As[16][128];
    __shared__ float Bs[16][128];

    const int tid = threadIdx.x;
    const int bm  = blockIdx.y * 128;
    const int bn  = blockIdx.x * 128;

    const int lrow = tid >> 2;          // 0..63
    const int lcol = (tid & 3) << 2;    // 0,4,8,12

    const float* Ap = g_A  + (size_t)(bm + lrow) * KDIM + lcol;
    const float* Bp = Wmat + (size_t)(bn + lrow) * KDIM + lcol;

    const int ty = tid >> 4;            // 0..15  -> rows ty*8..+7
    const int tx = tid & 15;            // 0..15  -> cols tx*8..+7

    float acc[8][8];
#pragma unroll
    for (int a = 0; a < 8; a++)
#pragma unroll
        for (int b = 0; b < 8; b++) acc[a][b] = 0.0f;

    float4 a0 = *(const float4*)(Ap);
    float4 a1 = *(const float4*)(Ap + (size_t)64 * KDIM);
    float4 b0 = *(const float4*)(Bp);
    float4 b1 = *(const float4*)(Bp + (size_t)64 * KDIM);

    const int ntiles = KDIM / 16;
    for (int t = 0; t < ntiles; t++) {
        As[lcol + 0][lrow]      = a0.x; As[lcol + 1][lrow]      = a0.y;
        As[lcol + 2][lrow]      = a0.z; As[lcol + 3][lrow]      = a0.w;
        As[lcol + 0][lrow + 64] = a1.x; As[lcol + 1][lrow + 64] = a1.y;
        As[lcol + 2][lrow + 64] = a1.z; As[lcol + 3][lrow + 64] = a1.w;
        Bs[lcol + 0][lrow]      = b0.x; Bs[lcol + 1][lrow]      = b0.y;
        Bs[lcol + 2][lrow]      = b0.z; Bs[lcol + 3][lrow]      = b0.w;
        Bs[lcol + 0][lrow + 64] = b1.x; Bs[lcol + 1][lrow + 64] = b1.y;
        Bs[lcol + 2][lrow + 64] = b1.z; Bs[lcol + 3][lrow + 64] = b1.w;
        __syncthreads();

        if (t + 1 < ntiles) {
            const float* Ap2 = Ap + (t + 1) * 16;
            const float* Bp2 = Bp + (t + 1) * 16;
            a0 = *(const float4*)(Ap2);
            a1 = *(const float4*)(Ap2 + (size_t)64 * KDIM);
            b0 = *(const float4*)(Bp2);
            b1 = *(const float4*)(Bp2 + (size_t)64 * KDIM);
        }

#pragma unroll
        for (int k = 0; k < 16; k++) {
            float ra[8], rb[8];
            *(float4*)&ra[0] = *(const float4*)&As[k][ty * 8];
            *(float4*)&ra[4] = *(const float4*)&As[k][ty * 8 + 4];
            *(float4*)&rb[0] = *(const float4*)&Bs[k][tx * 8];
            *(float4*)&rb[4] = *(const float4*)&Bs[k][tx * 8 + 4];
#pragma unroll
            for (int im = 0; im < 8; im++)
#pragma unroll
                for (int in = 0; in < 8; in++)
                    acc[im][in] += ra[im] * rb[in];
        }
        __syncthreads();
    }

    float bias_r[8];
#pragma unroll
    for (int in = 0; in < 8; in++) bias_r[in] = bias[bn + tx * 8 + in];

#pragma unroll
    for (int im = 0; im < 8; im++) {
        float* crow = g_zg + (size_t)(bm + ty * 8 + im) * NDIM + bn + tx * 8;
        float4 v0, v1;
        v0.x = acc[im][0] + bias_r[0]; v0.y = acc[im][1] + bias_r[1];
        v0.z = acc[im][2] + bias_r[2]; v0.w = acc[im][3] + bias_r[3];
        v1.x = acc[im][4] + bias_r[4]; v1.y = acc[im][5] + bias_r[5];
        v1.z = acc[im][6] + bias_r[6]; v1.w = acc[im][7] + bias_r[7];
        *(float4*)(crow)     = v0;
        *(float4*)(crow + 4) = v1;
    }
}

// ---------------------------------------------------------------------------
// Elementwise fixed-point half-step. step = 0 (h1/c1) or 1 (h2/c2).
// Writes recurrent_hidden ints (as float), output_hidden floats, and for
// step 0 overwrites the right half of g_A with h1_fl for GEMM2.
// Also produces deterministic per-block partial sums of log(z)+log(p).
// ---------------------------------------------------------------------------
__global__ void elem_kernel(const int* __restrict__ hidden,
                            float* __restrict__ out,
                            int step)
{
    __shared__ double sred[256];
    const int tid = threadIdx.x;
    const int idx = blockIdx.x * 256 + tid;       // 0 .. B_*G_-1
    const int i = idx >> 10;
    const int j = idx & 1023;

    const float* zrow = g_zg + (size_t)i * NDIM + j;
    const float xz = zrow[0];
    const float xg = zrow[G_];
    const float xf = zrow[2 * G_];
    const float xo = zrow[3 * G_];
    const float xp = zrow[4 * G_];

    const float z  = 0.96875f * sigm(xz) + 0.03125f;
    const float gg = tanhf(xg);
    const float f  = sigm(xf);
    const float o  = sigm(xo);
    const float p  = 0.96875f * sigm(xp) + 0.03125f;

    int zi = (int)(z * 1024.0f); if (zi < 1) zi = 1;
    int pi = (int)(p * 1024.0f); if (pi < 1) pi = 1;

    const int* hrow = hidden + (size_t)i * (4 * G_);
    const int cv = hrow[(2 + step) * G_ + j];
    const int hv = hrow[step * G_ + j];

    const float fg = f * gg;
    const int cn = (int)(((long long)cv * (long long)zi) >> 10) + (int)(fg * 8388608.0f);
    const float cfl = (float)cn * (1.0f / 8388608.0f);
    const float ot = o * tanhf(cfl);
    const int hn = (int)(((long long)hv * (long long)pi) >> 10) + (int)(ot * 8388608.0f);

    // recurrent_hidden: [h1 | h2 | c1 | c2] per row
    const size_t ro = (size_t)i * (4 * G_);
    out[OUT_REC + ro + (size_t)step * G_ + j]       = (float)hn;
    out[OUT_REC + ro + (size_t)(2 + step) * G_ + j] = (float)cn;

    // output_hidden: [h1_fl | h2_fl] per row
    const float hfl = (float)hn * (1.0f / 8388608.0f);
    out[OUT_OH + (size_t)i * (2 * G_) + (size_t)step * G_ + j] = hfl;

    if (step == 0)
        g_A[(size_t)i * KDIM + G_ + j] = hfl;

    // log-sum partials (deterministic tree reduce)
    sred[tid] = (double)(logf(z) + logf(p));
    __syncthreads();
#pragma unroll
    for (int s = 128; s > 0; s >>= 1) {
        if (tid < s) sred[tid] += sred[tid + s];
        __syncthreads();
    }
    if (tid == 0) g_part[step * 16384 + blockIdx.x] = sred[0];
}

// ---------------------------------------------------------------------------
// Final scalar: optimal_bits = -(sum of logs) / ln2
// ---------------------------------------------------------------------------
__global__ void bits_kernel(float* __restrict__ out, long long last_idx)
{
    __shared__ double sred[256];
    const int tid = threadIdx.x;
    double s = 0.0;
    for (int i = tid; i < 2 * 16384; i += 256) s += g_part[i];
    sred[tid] = s;
    __syncthreads();
#pragma unroll
    for (int k = 128; k > 0; k >>= 1) {
        if (tid < k) sred[tid] += sred[tid + k];
        __syncthreads();
    }
    if (tid == 0)
        out[last_idx] = (float)(-sred[0] / 0.6931471805599453);
}

// ---------------------------------------------------------------------------
extern "C" void kernel_launch(void* const* d_in, const int* in_sizes, int n_in,
                              void* d_out, int out_size)
{
    const float* inp    = (const float*)d_in[0];   // (4096, 1024)
    const int*   hidden = (const int*)  d_in[1];   // (4096, 4096) int32
    const float* W1     = (const float*)d_in[2];   // (5120, 2048)
    const float* b1     = (const float*)d_in[3];   // (5120,)
    const float* W2     = (const float*)d_in[4];
    const float* b2     = (const float*)d_in[5];
    float* out = (float*)d_out;

    const int elem_blocks = (B_ * G_) / 256;       // 16384
    dim3 gemm_grid(NDIM / 128, B_ / 128);          // (40, 32)

    prep_kernel<<<elem_blocks, 256>>>(inp, hidden);
    sgemm_kernel<<<gemm_grid, 256>>>(W1, b1);
    elem_kernel<<<elem_blocks, 256>>>(hidden, out, 0);
    sgemm_kernel<<<gemm_grid, 256>>>(W2, b2);
    elem_kernel<<<elem_blocks, 256>>>(hidden, out, 1);
    bits_kernel<<<1, 256>>>(out, (long long)out_size - 1);
}

// round 3
// speedup vs baseline: 2.9493x; 2.9493x over previous
#include <cuda_runtime.h>
#include <cuda_bf16.h>
#include <math.h>
#include <stdint.h>

// ---------------------------------------------------------------------------
// Problem constants
// ---------------------------------------------------------------------------
constexpr int B_  = 4096;    // batch
constexpr int G_  = 1024;    // gate width
constexpr int KD  = 2048;    // IN + g (source K)
constexpr int KP  = 6144;    // packed K for bf16x3 (3 * KD)
constexpr int ND  = 5120;    // out_dim
constexpr long long OUT_OH = (long long)B_ * 4 * G_;

// ---------------------------------------------------------------------------
// Static scratch (no allocations allowed)
// ---------------------------------------------------------------------------
__device__ __align__(256) __nv_bfloat16 g_A [(size_t)B_ * KP];   // 50 MB
__device__ __align__(256) __nv_bfloat16 g_W1[(size_t)ND * KP];   // 63 MB
__device__ __align__(256) __nv_bfloat16 g_W2[(size_t)ND * KP];   // 63 MB
__device__ __align__(256) float         g_zg[(size_t)B_ * ND];   // 84 MB
__device__ double g_part[2 * 16384];

// ---------------------------------------------------------------------------
// PTX helpers (all baseline sm_80+ features; no sm_100a-only instructions)
// ---------------------------------------------------------------------------
__device__ __forceinline__ uint32_t smem_u32(const void* p) {
    uint32_t a;
    asm("{ .reg .u64 t; cvta.to.shared.u64 t, %1; cvt.u32.u64 %0, t; }" : "=r"(a) : "l"(p));
    return a;
}
__device__ __forceinline__ void cp_async16(uint32_t dst, const void* src) {
    asm volatile("cp.async.cg.shared.global [%0], [%1], 16;" :: "r"(dst), "l"(src) : "memory");
}
#define CP_COMMIT()  asm volatile("cp.async.commit_group;" ::: "memory")
#define CP_WAIT(n)   asm volatile("cp.async.wait_group %0;" :: "n"(n) : "memory")

#define LDSM4(r0, r1, r2, r3, addr) \
    asm volatile("ldmatrix.sync.aligned.m8n8.x4.shared.b16 {%0,%1,%2,%3}, [%4];" \
                 : "=r"(r0), "=r"(r1), "=r"(r2), "=r"(r3) : "r"(addr))

#define MMA16816(d, a, b) \
    asm volatile("mma.sync.aligned.m16n8k16.row.col.f32.bf16.bf16.f32 " \
                 "{%0,%1,%2,%3}, {%4,%5,%6,%7}, {%8,%9}, {%0,%1,%2,%3};" \
                 : "+f"((d)[0]), "+f"((d)[1]), "+f"((d)[2]), "+f"((d)[3]) \
                 : "r"((a)[0]), "r"((a)[1]), "r"((a)[2]), "r"((a)[3]), \
                   "r"((b)[0]), "r"((b)[1]))

#define SWZ(o) ((o) ^ (((o) >> 3) & 0x70))

__device__ __forceinline__ float sigm(float x) { return 1.0f / (1.0f + expf(-x)); }

// ---------------------------------------------------------------------------
// Pack A' = bf16x3([input | h2_fl])  : pos k -> a0, 2048+k -> a1, 4096+k -> a0
// ---------------------------------------------------------------------------
__global__ void prep_kernel(const float* __restrict__ inp,
                            const int*   __restrict__ hidden)
{
    int idx = blockIdx.x * 256 + threadIdx.x;      // 0 .. B_*KD-1
    int i = idx >> 11;
    int k = idx & 2047;
    float x = (k < 1024) ? inp[(size_t)i * 1024 + k]
                         : (float)hidden[(size_t)i * 4096 + k] * (1.0f / 8388608.0f);
    __nv_bfloat16 a0 = __float2bfloat16(x);
    __nv_bfloat16 a1 = __float2bfloat16(x - __bfloat162float(a0));
    size_t base = (size_t)i * KP;
    g_A[base + k]        = a0;
    g_A[base + 2048 + k] = a1;
    g_A[base + 4096 + k] = a0;
}

// ---------------------------------------------------------------------------
// Pack W' = bf16x3(W) : pos k -> b0, 2048+k -> b0, 4096+k -> b1
// ---------------------------------------------------------------------------
__global__ void wconv_kernel(const float* __restrict__ Wsrc, int which)
{
    __nv_bfloat16* dst = which ? g_W2 : g_W1;
    int idx = blockIdx.x * 256 + threadIdx.x;      // 0 .. ND*KD-1
    int n = idx >> 11;
    int k = idx & 2047;
    float w = Wsrc[(size_t)n * KD + k];
    __nv_bfloat16 b0 = __float2bfloat16(w);
    __nv_bfloat16 b1 = __float2bfloat16(w - __bfloat162float(b0));
    size_t base = (size_t)n * KP;
    dst[base + k]        = b0;
    dst[base + 2048 + k] = b0;
    dst[base + 4096 + k] = b1;
}

// ---------------------------------------------------------------------------
// mma.sync bf16 GEMM:  g_zg = A'(B_ x KP) @ W'^T (ND x KP) + bias
// CTA tile 128x128, 8 warps (2Mx4N), warp tile 64x32, K-chunk 64,
// SW128-swizzled smem, 3-stage cp.async pipeline.
// ---------------------------------------------------------------------------
constexpr int TM = 128, TN = 128, KC = 64, STAGES = 3;
constexpr int A_BYTES = TM * 128;                 // 16384 per stage
constexpr int STAGE_BYTES = A_BYTES + TN * 128;   // 32768
constexpr int SMEM_TOTAL = STAGES * STAGE_BYTES;  // 98304
constexpr int NCHUNK = KP / KC;                   // 96

__global__ __launch_bounds__(256, 2)
void gemm_kernel(int which, const float* __restrict__ bias)
{
    extern __shared__ char smem[];
    const uint32_t sb = smem_u32(smem);
    const int tid  = threadIdx.x;
    const int wid  = tid >> 5;
    const int lane = tid & 31;
    const int bm = blockIdx.y * TM;
    const int bn = blockIdx.x * TN;
    const __nv_bfloat16* __restrict__ Ag = g_A;
    const __nv_bfloat16* __restrict__ Wg = which ? g_W2 : g_W1;

    // ---- producer setup: 8 x 16B cp.async chunks per thread per stage ----
    const char* srcb[8];
    uint32_t    dsto[8];
#pragma unroll
    for (int i = 0; i < 8; i++) {
        const int v = tid + 256 * i;               // 0..2047
        if (v < 1024) {                            // A tile: 128 rows x 8 grps
            const int row = v >> 3, grp = v & 7;
            srcb[i] = (const char*)(Ag + (size_t)(bm + row) * KP) + grp * 16;
            dsto[i] = SWZ(row * 128 + grp * 16);
        } else {                                   // B tile
            const int u = v - 1024;
            const int row = u >> 3, grp = u & 7;
            srcb[i] = (const char*)(Wg + (size_t)(bn + row) * KP) + grp * 16;
            dsto[i] = A_BYTES + SWZ(row * 128 + grp * 16);
        }
    }

    // ---- consumer setup: ldmatrix lane addressing ----
    const int wm = (wid & 1) * 64;                 // warp M offset
    const int wn = (wid >> 1) * 32;                // warp N offset
    const int q  = lane >> 3;                      // quad 0..3
    const int l7 = lane & 7;

    // A quads: q0=(mlow,klow) q1=(mhigh,klow) q2=(mlow,khigh) q3=(mhigh,khigh)
    uint32_t a_rt[4], a_xor[4];
#pragma unroll
    for (int mt = 0; mt < 4; mt++) {
        const int row = wm + mt * 16 + l7 + (q & 1) * 8;
        a_rt[mt]  = (uint32_t)row * 128;
        a_xor[mt] = (uint32_t)(row & 7) * 16;
    }
    const uint32_t a_kh = (uint32_t)(q >> 1) * 16;

    // B quads: q0=(nlow,klow) q1=(nlow,khigh) q2=(nhigh,klow) q3=(nhigh,khigh)
    uint32_t b_rt[2], b_xor[2];
#pragma unroll
    for (int nb2 = 0; nb2 < 2; nb2++) {
        const int row = wn + nb2 * 16 + l7 + (q >> 1) * 8;
        b_rt[nb2]  = (uint32_t)(A_BYTES + row * 128);
        b_xor[nb2] = (uint32_t)(row & 7) * 16;
    }
    const uint32_t b_kh = (uint32_t)(q & 1) * 16;

    float acc[4][4][4];
#pragma unroll
    for (int mt = 0; mt < 4; mt++)
#pragma unroll
        for (int nb = 0; nb < 4; nb++)
#pragma unroll
            for (int r = 0; r < 4; r++) acc[mt][nb][r] = 0.0f;

    // ---- prologue: issue stages 0,1 ----
#pragma unroll
    for (int s = 0; s < 2; s++) {
        const uint32_t sdst = sb + s * STAGE_BYTES;
#pragma unroll
        for (int i = 0; i < 8; i++)
            cp_async16(sdst + dsto[i], srcb[i] + (size_t)s * 128);
        CP_COMMIT();
    }

    // ---- main loop ----
    int sc = 0;   // compute stage index (c % 3)
    int sl = 2;   // load stage index ((c+2) % 3)
    for (int c = 0; c < NCHUNK; c++) {
        __syncthreads();                            // prev compute done before overwrite
        if (c + 2 < NCHUNK) {
            const uint32_t sdst = sb + sl * STAGE_BYTES;
            const size_t koff = (size_t)(c + 2) * 128;
#pragma unroll
            for (int i = 0; i < 8; i++)
                cp_async16(sdst + dsto[i], srcb[i] + koff);
        }
        CP_COMMIT();
        CP_WAIT(2);
        __syncthreads();                            // stage sc visible to all

        const uint32_t sA = sb + sc * STAGE_BYTES;
#pragma unroll
        for (int kk = 0; kk < 4; kk++) {
            const uint32_t kb = kk * 32;
            uint32_t af[4][4];
#pragma unroll
            for (int mt = 0; mt < 4; mt++)
                LDSM4(af[mt][0], af[mt][1], af[mt][2], af[mt][3],
                      sA + a_rt[mt] + ((kb + a_kh) ^ a_xor[mt]));
            uint32_t bf[4][2];
#pragma unroll
            for (int nb2 = 0; nb2 < 2; nb2++) {
                uint32_t r0, r1, r2, r3;
                LDSM4(r0, r1, r2, r3,
                      sA + b_rt[nb2] + ((kb + b_kh) ^ b_xor[nb2]));
                bf[nb2 * 2 + 0][0] = r0; bf[nb2 * 2 + 0][1] = r1;
                bf[nb2 * 2 + 1][0] = r2; bf[nb2 * 2 + 1][1] = r3;
            }
#pragma unroll
            for (int mt = 0; mt < 4; mt++)
#pragma unroll
                for (int nb = 0; nb < 4; nb++)
                    MMA16816(acc[mt][nb], af[mt], bf[nb]);
        }

        sc = (sc == 2) ? 0 : sc + 1;
        sl = (sl == 2) ? 0 : sl + 1;
    }

    // ---- epilogue: direct STG with bias ----
    const int trow = lane >> 2;
    const int tcol = (lane & 3) * 2;
#pragma unroll
    for (int mt = 0; mt < 4; mt++) {
        const int grow = bm + wm + mt * 16 + trow;
#pragma unroll
        for (int nb = 0; nb < 4; nb++) {
            const int gcol = bn + wn + nb * 8 + tcol;
            const float bz0 = __ldg(bias + gcol);
            const float bz1 = __ldg(bias + gcol + 1);
            float2 v0, v1;
            v0.x = acc[mt][nb][0] + bz0; v0.y = acc[mt][nb][1] + bz1;
            v1.x = acc[mt][nb][2] + bz0; v1.y = acc[mt][nb][3] + bz1;
            *(float2*)(g_zg + (size_t)grow * ND + gcol)       = v0;
            *(float2*)(g_zg + (size_t)(grow + 8) * ND + gcol) = v1;
        }
    }
}

// ---------------------------------------------------------------------------
// Elementwise fixed-point half-step (same math as reference)
// ---------------------------------------------------------------------------
__global__ void elem_kernel(const int* __restrict__ hidden,
                            float* __restrict__ out,
                            int step)
{
    __shared__ double sred[256];
    const int tid = threadIdx.x;
    const int idx = blockIdx.x * 256 + tid;       // 0 .. B_*G_-1
    const int i = idx >> 10;
    const int j = idx & 1023;

    const float* zrow = g_zg + (size_t)i * ND + j;
    const float xz = zrow[0];
    const float xg = zrow[G_];
    const float xf = zrow[2 * G_];
    const float xo = zrow[3 * G_];
    const float xp = zrow[4 * G_];

    const float z  = 0.96875f * sigm(xz) + 0.03125f;
    const float gg = tanhf(xg);
    const float f  = sigm(xf);
    const float o  = sigm(xo);
    const float p  = 0.96875f * sigm(xp) + 0.03125f;

    int zi = (int)(z * 1024.0f); if (zi < 1) zi = 1;
    int pi = (int)(p * 1024.0f); if (pi < 1) pi = 1;

    const int* hrow = hidden + (size_t)i * (4 * G_);
    const int cv = hrow[(2 + step) * G_ + j];
    const int hv = hrow[step * G_ + j];

    const float fg = f * gg;
    const int cn = (int)(((long long)cv * (long long)zi) >> 10) + (int)(fg * 8388608.0f);
    const float cfl = (float)cn * (1.0f / 8388608.0f);
    const float ot = o * tanhf(cfl);
    const int hn = (int)(((long long)hv * (long long)pi) >> 10) + (int)(ot * 8388608.0f);

    const size_t ro = (size_t)i * (4 * G_);
    out[ro + (size_t)step * G_ + j]       = (float)hn;
    out[ro + (size_t)(2 + step) * G_ + j] = (float)cn;

    const float hfl = (float)hn * (1.0f / 8388608.0f);
    out[OUT_OH + (size_t)i * (2 * G_) + (size_t)step * G_ + j] = hfl;

    if (step == 0) {
        // write h1_fl bf16x3 into packed A at source k = 1024 + j
        __nv_bfloat16 a0 = __float2bfloat16(hfl);
        __nv_bfloat16 a1 = __float2bfloat16(hfl - __bfloat162float(a0));
        size_t base = (size_t)i * KP;
        g_A[base + 1024 + j] = a0;
        g_A[base + 3072 + j] = a1;
        g_A[base + 5120 + j] = a0;
    }

    sred[tid] = (double)(logf(z) + logf(p));
    __syncthreads();
#pragma unroll
    for (int s = 128; s > 0; s >>= 1) {
        if (tid < s) sred[tid] += sred[tid + s];
        __syncthreads();
    }
    if (tid == 0) g_part[step * 16384 + blockIdx.x] = sred[0];
}

__global__ void bits_kernel(float* __restrict__ out, long long last_idx)
{
    __shared__ double sred[256];
    const int tid = threadIdx.x;
    double s = 0.0;
    for (int i = tid; i < 2 * 16384; i += 256) s += g_part[i];
    sred[tid] = s;
    __syncthreads();
#pragma unroll
    for (int k = 128; k > 0; k >>= 1) {
        if (tid < k) sred[tid] += sred[tid + k];
        __syncthreads();
    }
    if (tid == 0)
        out[last_idx] = (float)(-sred[0] / 0.6931471805599453);
}

// ---------------------------------------------------------------------------
extern "C" void kernel_launch(void* const* d_in, const int* in_sizes, int n_in,
                              void* d_out, int out_size)
{
    const float* inp    = (const float*)d_in[0];   // (4096, 1024)
    const int*   hidden = (const int*)  d_in[1];   // (4096, 4096)
    const float* W1     = (const float*)d_in[2];   // (5120, 2048)
    const float* b1     = (const float*)d_in[3];
    const float* W2     = (const float*)d_in[4];
    const float* b2     = (const float*)d_in[5];
    float* out = (float*)d_out;

    static bool attr_set = false;
    if (!attr_set) {
        cudaFuncSetAttribute(gemm_kernel, cudaFuncAttributeMaxDynamicSharedMemorySize, SMEM_TOTAL);
        attr_set = true;
    }

    const int elem_blocks = (B_ * G_) / 256;        // 16384
    dim3 gemm_grid(ND / TN, B_ / TM);               // (40, 32)

    prep_kernel <<<(B_ * KD) / 256, 256>>>(inp, hidden);
    wconv_kernel<<<(ND * KD) / 256, 256>>>(W1, 0);
    wconv_kernel<<<(ND * KD) / 256, 256>>>(W2, 1);

    gemm_kernel<<<gemm_grid, 256, SMEM_TOTAL>>>(0, b1);
    elem_kernel<<<elem_blocks, 256>>>(hidden, out, 0);
    gemm_kernel<<<gemm_grid, 256, SMEM_TOTAL>>>(1, b2);
    elem_kernel<<<elem_blocks, 256>>>(hidden, out, 1);
    bits_kernel<<<1, 256>>>(out, (long long)out_size - 1);
}

// round 4
// speedup vs baseline: 4.1196x; 1.3968x over previous
#include <cuda_runtime.h>
#include <cuda_fp16.h>
#include <math.h>
#include <stdint.h>

// ---------------------------------------------------------------------------
// Problem constants
// ---------------------------------------------------------------------------
constexpr int B_  = 4096;    // batch
constexpr int G_  = 1024;    // gate width
constexpr int KD  = 2048;    // IN + g (source K)
constexpr int KPA = 4096;    // packed K for A = [a0 | a1]
constexpr int ND  = 5120;    // out_dim
constexpr long long OUT_OH = (long long)B_ * 4 * G_;

// ---------------------------------------------------------------------------
// Static scratch (no allocations allowed)
// ---------------------------------------------------------------------------
__device__ __align__(256) __half g_A [(size_t)B_ * KPA];   // 33.5 MB
__device__ __align__(256) __half g_W1[(size_t)ND * KD];    // 21 MB
__device__ __align__(256) __half g_W2[(size_t)ND * KD];    // 21 MB
__device__ __align__(256) float  g_zg[(size_t)B_ * ND];    // 84 MB
__device__ double g_part[2 * 16384];

// ---------------------------------------------------------------------------
// PTX helpers (all baseline sm_80+ features)
// ---------------------------------------------------------------------------
__device__ __forceinline__ uint32_t smem_u32(const void* p) {
    uint32_t a;
    asm("{ .reg .u64 t; cvta.to.shared.u64 t, %1; cvt.u32.u64 %0, t; }" : "=r"(a) : "l"(p));
    return a;
}
__device__ __forceinline__ void cp_async16(uint32_t dst, const void* src) {
    asm volatile("cp.async.cg.shared.global [%0], [%1], 16;" :: "r"(dst), "l"(src) : "memory");
}
#define CP_COMMIT()  asm volatile("cp.async.commit_group;" ::: "memory")
#define CP_WAIT(n)   asm volatile("cp.async.wait_group %0;" :: "n"(n) : "memory")

#define LDSM4(r0, r1, r2, r3, addr) \
    asm volatile("ldmatrix.sync.aligned.m8n8.x4.shared.b16 {%0,%1,%2,%3}, [%4];" \
                 : "=r"(r0), "=r"(r1), "=r"(r2), "=r"(r3) : "r"(addr))

#define MMA16816(d, a, b) \
    asm volatile("mma.sync.aligned.m16n8k16.row.col.f32.f16.f16.f32 " \
                 "{%0,%1,%2,%3}, {%4,%5,%6,%7}, {%8,%9}, {%0,%1,%2,%3};" \
                 : "+f"((d)[0]), "+f"((d)[1]), "+f"((d)[2]), "+f"((d)[3]) \
                 : "r"((a)[0]), "r"((a)[1]), "r"((a)[2]), "r"((a)[3]), \
                   "r"((b)[0]), "r"((b)[1]))

#define SWZ(o) ((o) ^ (((o) >> 3) & 0x70))

__device__ __forceinline__ float sigm(float x) { return 1.0f / (1.0f + expf(-x)); }

// ---------------------------------------------------------------------------
// Pack A' = [a0 | a1] fp16 split of [input | h2_fl]
// ---------------------------------------------------------------------------
__global__ void prep_kernel(const float* __restrict__ inp,
                            const int*   __restrict__ hidden)
{
    int idx = blockIdx.x * 256 + threadIdx.x;      // 0 .. B_*KD-1
    int i = idx >> 11;
    int k = idx & 2047;
    float x = (k < 1024) ? inp[(size_t)i * 1024 + k]
                         : (float)hidden[(size_t)i * 4096 + k] * (1.0f / 8388608.0f);
    __half a0 = __float2half_rn(x);
    __half a1 = __float2half_rn(x - __half2float(a0));
    size_t base = (size_t)i * KPA;
    g_A[base + k]        = a0;
    g_A[base + 2048 + k] = a1;
}

// ---------------------------------------------------------------------------
// W -> fp16 (single rounding; A carries the split)
// ---------------------------------------------------------------------------
__global__ void wconv_kernel(const float* __restrict__ Wsrc, int which)
{
    __half* dst = which ? g_W2 : g_W1;
    int idx = blockIdx.x * 256 + threadIdx.x;      // 0 .. ND*KD-1
    dst[idx] = __float2half_rn(Wsrc[idx]);
}

// ---------------------------------------------------------------------------
// mma.sync fp16 GEMM:  g_zg = A'(B_ x 4096) @ [W|W]^T + bias
// CTA tile 128x128, 8 warps (2Mx4N), warp tile 64x32, K-chunk 64,
// SW128-swizzled smem, 3-stage cp.async pipeline.
// B chunks repeat modulo 32 (b0 used for both halves of the split).
// ---------------------------------------------------------------------------
constexpr int TM = 128, TN = 128, STAGES = 3;
constexpr int A_BYTES = TM * 128;                 // 16384 per stage
constexpr int STAGE_BYTES = A_BYTES + TN * 128;   // 32768
constexpr int SMEM_TOTAL = STAGES * STAGE_BYTES;  // 98304
constexpr int NCHUNK = KPA / 64;                  // 64

__global__ __launch_bounds__(256, 2)
void gemm_kernel(int which, const float* __restrict__ bias)
{
    extern __shared__ char smem[];
    const uint32_t sb = smem_u32(smem);
    const int tid  = threadIdx.x;
    const int wid  = tid >> 5;
    const int lane = tid & 31;
    const int bm = blockIdx.y * TM;
    const int bn = blockIdx.x * TN;
    const __half* __restrict__ Ag = g_A;
    const __half* __restrict__ Wg = which ? g_W2 : g_W1;

    // ---- producer setup: 8 x 16B cp.async per thread per stage ----
    // i = 0..3 -> A tile rows (stride KPA), i = 4..7 -> B tile rows (stride KD)
    const char* srcb[8];
    uint32_t    dsto[8];
#pragma unroll
    for (int i = 0; i < 8; i++) {
        const int v = tid + 256 * i;               // 0..2047
        if (v < 1024) {                            // A: 128 rows x 8 grps
            const int row = v >> 3, grp = v & 7;
            srcb[i] = (const char*)(Ag + (size_t)(bm + row) * KPA) + grp * 16;
            dsto[i] = SWZ(row * 128 + grp * 16);
        } else {                                   // B: 128 rows x 8 grps
            const int u = v - 1024;
            const int row = u >> 3, grp = u & 7;
            srcb[i] = (const char*)(Wg + (size_t)(bn + row) * KD) + grp * 16;
            dsto[i] = A_BYTES + SWZ(row * 128 + grp * 16);
        }
    }

    // ---- consumer setup: ldmatrix lane addressing ----
    const int wm = (wid & 1) * 64;                 // warp M offset
    const int wn = (wid >> 1) * 32;                // warp N offset
    const int q  = lane >> 3;                      // quad 0..3
    const int l7 = lane & 7;

    uint32_t a_rt[4], a_xor[4];
#pragma unroll
    for (int mt = 0; mt < 4; mt++) {
        const int row = wm + mt * 16 + l7 + (q & 1) * 8;
        a_rt[mt]  = (uint32_t)row * 128;
        a_xor[mt] = (uint32_t)(row & 7) * 16;
    }
    const uint32_t a_kh = (uint32_t)(q >> 1) * 16;

    uint32_t b_rt[2], b_xor[2];
#pragma unroll
    for (int nb2 = 0; nb2 < 2; nb2++) {
        const int row = wn + nb2 * 16 + l7 + (q >> 1) * 8;
        b_rt[nb2]  = (uint32_t)(A_BYTES + row * 128);
        b_xor[nb2] = (uint32_t)(row & 7) * 16;
    }
    const uint32_t b_kh = (uint32_t)(q & 1) * 16;

    float acc[4][4][4];
#pragma unroll
    for (int mt = 0; mt < 4; mt++)
#pragma unroll
        for (int nb = 0; nb < 4; nb++)
#pragma unroll
            for (int r = 0; r < 4; r++) acc[mt][nb][r] = 0.0f;

    // ---- prologue: issue stages 0,1 (chunks 0,1; B chunk index == c for c<32) ----
#pragma unroll
    for (int s = 0; s < 2; s++) {
        const uint32_t sdst = sb + s * STAGE_BYTES;
#pragma unroll
        for (int i = 0; i < 8; i++)
            cp_async16(sdst + dsto[i], srcb[i] + (size_t)s * 128);
        CP_COMMIT();
    }

    // ---- main loop ----
    int sc = 0;   // compute stage
    int sl = 2;   // load stage
    for (int c = 0; c < NCHUNK; c++) {
        __syncthreads();                            // prev compute done before overwrite
        if (c + 2 < NCHUNK) {
            const uint32_t sdst = sb + sl * STAGE_BYTES;
            const size_t koffA = (size_t)(c + 2) * 128;
            const size_t koffB = (size_t)((c + 2) & 31) * 128;
#pragma unroll
            for (int i = 0; i < 4; i++)
                cp_async16(sdst + dsto[i], srcb[i] + koffA);
#pragma unroll
            for (int i = 4; i < 8; i++)
                cp_async16(sdst + dsto[i], srcb[i] + koffB);
        }
        CP_COMMIT();
        CP_WAIT(2);
        __syncthreads();                            // stage sc visible

        const uint32_t sA = sb + sc * STAGE_BYTES;
#pragma unroll
        for (int kk = 0; kk < 4; kk++) {
            const uint32_t kb = kk * 32;
            uint32_t af[4][4];
#pragma unroll
            for (int mt = 0; mt < 4; mt++)
                LDSM4(af[mt][0], af[mt][1], af[mt][2], af[mt][3],
                      sA + a_rt[mt] + ((kb + a_kh) ^ a_xor[mt]));
            uint32_t bf[4][2];
#pragma unroll
            for (int nb2 = 0; nb2 < 2; nb2++) {
                uint32_t r0, r1, r2, r3;
                LDSM4(r0, r1, r2, r3,
                      sA + b_rt[nb2] + ((kb + b_kh) ^ b_xor[nb2]));
                bf[nb2 * 2 + 0][0] = r0; bf[nb2 * 2 + 0][1] = r1;
                bf[nb2 * 2 + 1][0] = r2; bf[nb2 * 2 + 1][1] = r3;
            }
#pragma unroll
            for (int mt = 0; mt < 4; mt++)
#pragma unroll
                for (int nb = 0; nb < 4; nb++)
                    MMA16816(acc[mt][nb], af[mt], bf[nb]);
        }

        sc = (sc == 2) ? 0 : sc + 1;
        sl = (sl == 2) ? 0 : sl + 1;
    }

    // ---- epilogue: direct STG with bias ----
    const int trow = lane >> 2;
    const int tcol = (lane & 3) * 2;
#pragma unroll
    for (int mt = 0; mt < 4; mt++) {
        const int grow = bm + wm + mt * 16 + trow;
#pragma unroll
        for (int nb = 0; nb < 4; nb++) {
            const int gcol = bn + wn + nb * 8 + tcol;
            const float bz0 = __ldg(bias + gcol);
            const float bz1 = __ldg(bias + gcol + 1);
            float2 v0, v1;
            v0.x = acc[mt][nb][0] + bz0; v0.y = acc[mt][nb][1] + bz1;
            v1.x = acc[mt][nb][2] + bz0; v1.y = acc[mt][nb][3] + bz1;
            *(float2*)(g_zg + (size_t)grow * ND + gcol)       = v0;
            *(float2*)(g_zg + (size_t)(grow + 8) * ND + gcol) = v1;
        }
    }
}

// ---------------------------------------------------------------------------
// Elementwise fixed-point half-step (same math as reference)
// ---------------------------------------------------------------------------
__global__ void elem_kernel(const int* __restrict__ hidden,
                            float* __restrict__ out,
                            int step)
{
    __shared__ double sred[256];
    const int tid = threadIdx.x;
    const int idx = blockIdx.x * 256 + tid;       // 0 .. B_*G_-1
    const int i = idx >> 10;
    const int j = idx & 1023;

    const float* zrow = g_zg + (size_t)i * ND + j;
    const float xz = zrow[0];
    const float xg = zrow[G_];
    const float xf = zrow[2 * G_];
    const float xo = zrow[3 * G_];
    const float xp = zrow[4 * G_];

    const float z  = 0.96875f * sigm(xz) + 0.03125f;
    const float gg = tanhf(xg);
    const float f  = sigm(xf);
    const float o  = sigm(xo);
    const float p  = 0.96875f * sigm(xp) + 0.03125f;

    int zi = (int)(z * 1024.0f); if (zi < 1) zi = 1;
    int pi = (int)(p * 1024.0f); if (pi < 1) pi = 1;

    const int* hrow = hidden + (size_t)i * (4 * G_);
    const int cv = hrow[(2 + step) * G_ + j];
    const int hv = hrow[step * G_ + j];

    const float fg = f * gg;
    const int cn = (int)(((long long)cv * (long long)zi) >> 10) + (int)(fg * 8388608.0f);
    const float cfl = (float)cn * (1.0f / 8388608.0f);
    const float ot = o * tanhf(cfl);
    const int hn = (int)(((long long)hv * (long long)pi) >> 10) + (int)(ot * 8388608.0f);

    const size_t ro = (size_t)i * (4 * G_);
    out[ro + (size_t)step * G_ + j]       = (float)hn;
    out[ro + (size_t)(2 + step) * G_ + j] = (float)cn;

    const float hfl = (float)hn * (1.0f / 8388608.0f);
    out[OUT_OH + (size_t)i * (2 * G_) + (size_t)step * G_ + j] = hfl;

    if (step == 0) {
        // write h1_fl fp16 split into packed A at source k = 1024 + j
        __half a0 = __float2half_rn(hfl);
        __half a1 = __float2half_rn(hfl - __half2float(a0));
        size_t base = (size_t)i * KPA;
        g_A[base + 1024 + j] = a0;
        g_A[base + 3072 + j] = a1;
    }

    sred[tid] = (double)(logf(z) + logf(p));
    __syncthreads();
#pragma unroll
    for (int s = 128; s > 0; s >>= 1) {
        if (tid < s) sred[tid] += sred[tid + s];
        __syncthreads();
    }
    if (tid == 0) g_part[step * 16384 + blockIdx.x] = sred[0];
}

__global__ void bits_kernel(float* __restrict__ out, long long last_idx)
{
    __shared__ double sred[256];
    const int tid = threadIdx.x;
    double s = 0.0;
    for (int i = tid; i < 2 * 16384; i += 256) s += g_part[i];
    sred[tid] = s;
    __syncthreads();
#pragma unroll
    for (int k = 128; k > 0; k >>= 1) {
        if (tid < k) sred[tid] += sred[tid + k];
        __syncthreads();
    }
    if (tid == 0)
        out[last_idx] = (float)(-sred[0] / 0.6931471805599453);
}

// ---------------------------------------------------------------------------
extern "C" void kernel_launch(void* const* d_in, const int* in_sizes, int n_in,
                              void* d_out, int out_size)
{
    const float* inp    = (const float*)d_in[0];   // (4096, 1024)
    const int*   hidden = (const int*)  d_in[1];   // (4096, 4096)
    const float* W1     = (const float*)d_in[2];   // (5120, 2048)
    const float* b1     = (const float*)d_in[3];
    const float* W2     = (const float*)d_in[4];
    const float* b2     = (const float*)d_in[5];
    float* out = (float*)d_out;

    static bool attr_set = false;
    if (!attr_set) {
        cudaFuncSetAttribute(gemm_kernel, cudaFuncAttributeMaxDynamicSharedMemorySize, SMEM_TOTAL);
        attr_set = true;
    }

    const int elem_blocks = (B_ * G_) / 256;        // 16384
    dim3 gemm_grid(ND / TN, B_ / TM);               // (40, 32)

    prep_kernel <<<(B_ * KD) / 256, 256>>>(inp, hidden);
    wconv_kernel<<<(ND * KD) / 256, 256>>>(W1, 0);
    wconv_kernel<<<(ND * KD) / 256, 256>>>(W2, 1);

    gemm_kernel<<<gemm_grid, 256, SMEM_TOTAL>>>(0, b1);
    elem_kernel<<<elem_blocks, 256>>>(hidden, out, 0);
    gemm_kernel<<<gemm_grid, 256, SMEM_TOTAL>>>(1, b2);
    elem_kernel<<<elem_blocks, 256>>>(hidden, out, 1);
    bits_kernel<<<1, 256>>>(out, (long long)out_size - 1);
}

// round 5
// speedup vs baseline: 6.6941x; 1.6249x over previous
#include <cuda_runtime.h>
#include <cuda_fp16.h>
#include <math.h>
#include <stdint.h>

// ---------------------------------------------------------------------------
// Problem constants
// ---------------------------------------------------------------------------
constexpr int B_  = 4096;    // batch
constexpr int G_  = 1024;    // gate width
constexpr int KD  = 2048;    // IN + g  (GEMM K — plain fp16 both sides)
constexpr int ND  = 5120;    // out_dim
constexpr long long OUT_OH = (long long)B_ * 4 * G_;

// ---------------------------------------------------------------------------
// Static scratch (no allocations allowed)
// ---------------------------------------------------------------------------
__device__ __align__(256) __half g_A [(size_t)B_ * KD];    // 16.8 MB
__device__ __align__(256) __half g_W1[(size_t)ND * KD];    // 21 MB
__device__ __align__(256) __half g_W2[(size_t)ND * KD];    // 21 MB
__device__ __align__(256) float  g_zg[(size_t)B_ * ND];    // 84 MB
__device__ double g_part[2 * 16384];

// ---------------------------------------------------------------------------
// PTX helpers (all baseline sm_80+ features)
// ---------------------------------------------------------------------------
__device__ __forceinline__ uint32_t smem_u32(const void* p) {
    uint32_t a;
    asm("{ .reg .u64 t; cvta.to.shared.u64 t, %1; cvt.u32.u64 %0, t; }" : "=r"(a) : "l"(p));
    return a;
}
__device__ __forceinline__ void cp_async16(uint32_t dst, const void* src) {
    asm volatile("cp.async.cg.shared.global [%0], [%1], 16;" :: "r"(dst), "l"(src) : "memory");
}
#define CP_COMMIT()  asm volatile("cp.async.commit_group;" ::: "memory")
#define CP_WAIT(n)   asm volatile("cp.async.wait_group %0;" :: "n"(n) : "memory")

#define LDSM4(r0, r1, r2, r3, addr) \
    asm volatile("ldmatrix.sync.aligned.m8n8.x4.shared.b16 {%0,%1,%2,%3}, [%4];" \
                 : "=r"(r0), "=r"(r1), "=r"(r2), "=r"(r3) : "r"(addr))

#define MMA16816(d, a, b) \
    asm volatile("mma.sync.aligned.m16n8k16.row.col.f32.f16.f16.f32 " \
                 "{%0,%1,%2,%3}, {%4,%5,%6,%7}, {%8,%9}, {%0,%1,%2,%3};" \
                 : "+f"((d)[0]), "+f"((d)[1]), "+f"((d)[2]), "+f"((d)[3]) \
                 : "r"((a)[0]), "r"((a)[1]), "r"((a)[2]), "r"((a)[3]), \
                   "r"((b)[0]), "r"((b)[1]))

#define SWZ(o) ((o) ^ (((o) >> 3) & 0x70))

__device__ __forceinline__ float sigm(float x) { return 1.0f / (1.0f + expf(-x)); }

// ---------------------------------------------------------------------------
// Pack A = fp16([input | h2_fl])
// ---------------------------------------------------------------------------
__global__ void prep_kernel(const float* __restrict__ inp,
                            const int*   __restrict__ hidden)
{
    int idx = blockIdx.x * 256 + threadIdx.x;      // 0 .. B_*KD-1
    int i = idx >> 11;
    int k = idx & 2047;
    float x = (k < 1024) ? inp[(size_t)i * 1024 + k]
                         : (float)hidden[(size_t)i * 4096 + k] * (1.0f / 8388608.0f);
    g_A[idx] = __float2half_rn(x);
}

// ---------------------------------------------------------------------------
// W -> fp16
// ---------------------------------------------------------------------------
__global__ void wconv_kernel(const float* __restrict__ Wsrc, int which)
{
    __half* dst = which ? g_W2 : g_W1;
    int idx = blockIdx.x * 256 + threadIdx.x;      // 0 .. ND*KD-1
    dst[idx] = __float2half_rn(Wsrc[idx]);
}

// ---------------------------------------------------------------------------
// mma.sync fp16 GEMM:  g_zg = A(B_ x 2048) @ W^T (ND x 2048) + bias
// CTA tile 128x128, 8 warps (2Mx4N), warp tile 64x32, K-chunk 64,
// SW128-swizzled smem, 3-stage cp.async pipeline, ONE barrier per chunk.
// ---------------------------------------------------------------------------
constexpr int TM = 128, TN = 128, STAGES = 3;
constexpr int A_BYTES = TM * 128;                 // 16384 per stage
constexpr int STAGE_BYTES = A_BYTES + TN * 128;   // 32768
constexpr int SMEM_TOTAL = STAGES * STAGE_BYTES;  // 98304
constexpr int NCHUNK = KD / 64;                   // 32

__global__ __launch_bounds__(256, 2)
void gemm_kernel(int which, const float* __restrict__ bias)
{
    extern __shared__ char smem[];
    const uint32_t sb = smem_u32(smem);
    const int tid  = threadIdx.x;
    const int wid  = tid >> 5;
    const int lane = tid & 31;
    const int bm = blockIdx.y * TM;
    const int bn = blockIdx.x * TN;
    const __half* __restrict__ Ag = g_A;
    const __half* __restrict__ Wg = which ? g_W2 : g_W1;

    // ---- producer setup: 8 x 16B cp.async per thread per stage ----
    const char* srcb[8];
    uint32_t    dsto[8];
#pragma unroll
    for (int i = 0; i < 8; i++) {
        const int v = tid + 256 * i;               // 0..2047
        if (v < 1024) {                            // A: 128 rows x 8 grps
            const int row = v >> 3, grp = v & 7;
            srcb[i] = (const char*)(Ag + (size_t)(bm + row) * KD) + grp * 16;
            dsto[i] = SWZ(row * 128 + grp * 16);
        } else {                                   // B: 128 rows x 8 grps
            const int u = v - 1024;
            const int row = u >> 3, grp = u & 7;
            srcb[i] = (const char*)(Wg + (size_t)(bn + row) * KD) + grp * 16;
            dsto[i] = A_BYTES + SWZ(row * 128 + grp * 16);
        }
    }

    // ---- consumer setup: ldmatrix lane addressing ----
    const int wm = (wid & 1) * 64;                 // warp M offset
    const int wn = (wid >> 1) * 32;                // warp N offset
    const int q  = lane >> 3;                      // quad 0..3
    const int l7 = lane & 7;

    uint32_t a_rt[4], a_xor[4];
#pragma unroll
    for (int mt = 0; mt < 4; mt++) {
        const int row = wm + mt * 16 + l7 + (q & 1) * 8;
        a_rt[mt]  = (uint32_t)row * 128;
        a_xor[mt] = (uint32_t)(row & 7) * 16;
    }
    const uint32_t a_kh = (uint32_t)(q >> 1) * 16;

    uint32_t b_rt[2], b_xor[2];
#pragma unroll
    for (int nb2 = 0; nb2 < 2; nb2++) {
        const int row = wn + nb2 * 16 + l7 + (q >> 1) * 8;
        b_rt[nb2]  = (uint32_t)(A_BYTES + row * 128);
        b_xor[nb2] = (uint32_t)(row & 7) * 16;
    }
    const uint32_t b_kh = (uint32_t)(q & 1) * 16;

    float acc[4][4][4];
#pragma unroll
    for (int mt = 0; mt < 4; mt++)
#pragma unroll
        for (int nb = 0; nb < 4; nb++)
#pragma unroll
            for (int r = 0; r < 4; r++) acc[mt][nb][r] = 0.0f;

    // ---- prologue: issue chunks 0,1 into stages 0,1 ----
#pragma unroll
    for (int s = 0; s < 2; s++) {
        const uint32_t sdst = sb + s * STAGE_BYTES;
#pragma unroll
        for (int i = 0; i < 8; i++)
            cp_async16(sdst + dsto[i], srcb[i] + (size_t)s * 128);
        CP_COMMIT();
    }

    // ---- main loop: ONE barrier per chunk ----
    // Invariant: after barrier of iter c, all warps finished reading stage
    // (c-1)%3 == (c+2)%3, so it is safe to refill it with chunk c+2.
    int sc = 0;   // compute stage
    int sl = 2;   // load stage
    for (int c = 0; c < NCHUNK; c++) {
        CP_WAIT(1);                                 // chunk c arrived (this thread)
        __syncthreads();                            // visible to all threads
        if (c + 2 < NCHUNK) {
            const uint32_t sdst = sb + sl * STAGE_BYTES;
            const size_t koff = (size_t)(c + 2) * 128;
#pragma unroll
            for (int i = 0; i < 8; i++)
                cp_async16(sdst + dsto[i], srcb[i] + koff);
        }
        CP_COMMIT();

        const uint32_t sA = sb + sc * STAGE_BYTES;
#pragma unroll
        for (int kk = 0; kk < 4; kk++) {
            const uint32_t kb = kk * 32;
            uint32_t af[4][4];
#pragma unroll
            for (int mt = 0; mt < 4; mt++)
                LDSM4(af[mt][0], af[mt][1], af[mt][2], af[mt][3],
                      sA + a_rt[mt] + ((kb + a_kh) ^ a_xor[mt]));
            uint32_t bf[4][2];
#pragma unroll
            for (int nb2 = 0; nb2 < 2; nb2++) {
                uint32_t r0, r1, r2, r3;
                LDSM4(r0, r1, r2, r3,
                      sA + b_rt[nb2] + ((kb + b_kh) ^ b_xor[nb2]));
                bf[nb2 * 2 + 0][0] = r0; bf[nb2 * 2 + 0][1] = r1;
                bf[nb2 * 2 + 1][0] = r2; bf[nb2 * 2 + 1][1] = r3;
            }
#pragma unroll
            for (int mt = 0; mt < 4; mt++)
#pragma unroll
                for (int nb = 0; nb < 4; nb++)
                    MMA16816(acc[mt][nb], af[mt], bf[nb]);
        }

        sc = (sc == 2) ? 0 : sc + 1;
        sl = (sl == 2) ? 0 : sl + 1;
    }

    // ---- epilogue: direct STG with bias ----
    const int trow = lane >> 2;
    const int tcol = (lane & 3) * 2;
#pragma unroll
    for (int mt = 0; mt < 4; mt++) {
        const int grow = bm + wm + mt * 16 + trow;
#pragma unroll
        for (int nb = 0; nb < 4; nb++) {
            const int gcol = bn + wn + nb * 8 + tcol;
            const float bz0 = __ldg(bias + gcol);
            const float bz1 = __ldg(bias + gcol + 1);
            float2 v0, v1;
            v0.x = acc[mt][nb][0] + bz0; v0.y = acc[mt][nb][1] + bz1;
            v1.x = acc[mt][nb][2] + bz0; v1.y = acc[mt][nb][3] + bz1;
            *(float2*)(g_zg + (size_t)grow * ND + gcol)       = v0;
            *(float2*)(g_zg + (size_t)(grow + 8) * ND + gcol) = v1;
        }
    }
}

// ---------------------------------------------------------------------------
// Elementwise fixed-point half-step (same math as reference)
// ---------------------------------------------------------------------------
__global__ void elem_kernel(const int* __restrict__ hidden,
                            float* __restrict__ out,
                            int step)
{
    __shared__ double sred[256];
    const int tid = threadIdx.x;
    const int idx = blockIdx.x * 256 + tid;       // 0 .. B_*G_-1
    const int i = idx >> 10;
    const int j = idx & 1023;

    const float* zrow = g_zg + (size_t)i * ND + j;
    const float xz = zrow[0];
    const float xg = zrow[G_];
    const float xf = zrow[2 * G_];
    const float xo = zrow[3 * G_];
    const float xp = zrow[4 * G_];

    const float z  = 0.96875f * sigm(xz) + 0.03125f;
    const float gg = tanhf(xg);
    const float f  = sigm(xf);
    const float o  = sigm(xo);
    const float p  = 0.96875f * sigm(xp) + 0.03125f;

    int zi = (int)(z * 1024.0f); if (zi < 1) zi = 1;
    int pi = (int)(p * 1024.0f); if (pi < 1) pi = 1;

    const int* hrow = hidden + (size_t)i * (4 * G_);
    const int cv = hrow[(2 + step) * G_ + j];
    const int hv = hrow[step * G_ + j];

    const float fg = f * gg;
    const int cn = (int)(((long long)cv * (long long)zi) >> 10) + (int)(fg * 8388608.0f);
    const float cfl = (float)cn * (1.0f / 8388608.0f);
    const float ot = o * tanhf(cfl);
    const int hn = (int)(((long long)hv * (long long)pi) >> 10) + (int)(ot * 8388608.0f);

    const size_t ro = (size_t)i * (4 * G_);
    out[ro + (size_t)step * G_ + j]       = (float)hn;
    out[ro + (size_t)(2 + step) * G_ + j] = (float)cn;

    const float hfl = (float)hn * (1.0f / 8388608.0f);
    out[OUT_OH + (size_t)i * (2 * G_) + (size_t)step * G_ + j] = hfl;

    if (step == 0)
        g_A[(size_t)i * KD + 1024 + j] = __float2half_rn(hfl);

    sred[tid] = (double)(logf(z) + logf(p));
    __syncthreads();
#pragma unroll
    for (int s = 128; s > 0; s >>= 1) {
        if (tid < s) sred[tid] += sred[tid + s];
        __syncthreads();
    }
    if (tid == 0) g_part[step * 16384 + blockIdx.x] = sred[0];
}

__global__ void bits_kernel(float* __restrict__ out, long long last_idx)
{
    __shared__ double sred[256];
    const int tid = threadIdx.x;
    double s = 0.0;
    for (int i = tid; i < 2 * 16384; i += 256) s += g_part[i];
    sred[tid] = s;
    __syncthreads();
#pragma unroll
    for (int k = 128; k > 0; k >>= 1) {
        if (tid < k) sred[tid] += sred[tid + k];
        __syncthreads();
    }
    if (tid == 0)
        out[last_idx] = (float)(-sred[0] / 0.6931471805599453);
}

// ---------------------------------------------------------------------------
extern "C" void kernel_launch(void* const* d_in, const int* in_sizes, int n_in,
                              void* d_out, int out_size)
{
    const float* inp    = (const float*)d_in[0];   // (4096, 1024)
    const int*   hidden = (const int*)  d_in[1];   // (4096, 4096)
    const float* W1     = (const float*)d_in[2];   // (5120, 2048)
    const float* b1     = (const float*)d_in[3];
    const float* W2     = (const float*)d_in[4];
    const float* b2     = (const float*)d_in[5];
    float* out = (float*)d_out;

    static bool attr_set = false;
    if (!attr_set) {
        cudaFuncSetAttribute(gemm_kernel, cudaFuncAttributeMaxDynamicSharedMemorySize, SMEM_TOTAL);
        attr_set = true;
    }

    const int elem_blocks = (B_ * G_) / 256;        // 16384
    dim3 gemm_grid(ND / TN, B_ / TM);               // (40, 32)

    prep_kernel <<<(B_ * KD) / 256, 256>>>(inp, hidden);
    wconv_kernel<<<(ND * KD) / 256, 256>>>(W1, 0);
    wconv_kernel<<<(ND * KD) / 256, 256>>>(W2, 1);

    gemm_kernel<<<gemm_grid, 256, SMEM_TOTAL>>>(0, b1);
    elem_kernel<<<elem_blocks, 256>>>(hidden, out, 0);
    gemm_kernel<<<gemm_grid, 256, SMEM_TOTAL>>>(1, b2);
    elem_kernel<<<elem_blocks, 256>>>(hidden, out, 1);
    bits_kernel<<<1, 256>>>(out, (long long)out_size - 1);
}